// round 1
// baseline (speedup 1.0000x reference)
#include <cuda_runtime.h>
#include <cuda_bf16.h>
#include <math.h>

// Problem constants
#define NB   64
#define NC   64
#define NH   56
#define NW   56
#define NE   8
#define HW   (NH*NW)          // 3136
#define CHW  (NC*HW)          // 200704
#define OUT_MAIN (NB*CHW)     // 12845056

// Scratch: conv1 output per (b, slot)  -> 64*2*200704 floats = 411 MB
__device__ float g_y1[NB * 2 * CHW];
__device__ int   g_eidx[NB * 2];
__device__ float g_ewt[NB * 2];

// ---------------------------------------------------------------------------
// Gate: mean pool -> linear -> top-2 softmax. Writes expert routing globals
// and the nonzero dense_w entries (output tail is pre-zeroed by memset).
// ---------------------------------------------------------------------------
__global__ void gate_kernel(const float* __restrict__ x,
                            const float* __restrict__ gw,
                            const float* __restrict__ gb,
                            float* __restrict__ dw_out /* may be null */)
{
    int b = blockIdx.x;
    __shared__ float pooled[NC];
    __shared__ float logits[NE];

    int warp = threadIdx.x >> 5;
    int lane = threadIdx.x & 31;

    // warp per channel (8 warps x 8 channels each)
    for (int c = warp; c < NC; c += 8) {
        const float* p = x + ((size_t)b * NC + c) * HW;
        float s = 0.f;
        for (int i = lane; i < HW; i += 32) s += p[i];
        #pragma unroll
        for (int o = 16; o > 0; o >>= 1) s += __shfl_xor_sync(0xffffffffu, s, o);
        if (lane == 0) pooled[c] = s * (1.0f / (float)HW);
    }
    __syncthreads();

    if (threadIdx.x < NE) {
        int e = threadIdx.x;
        float s = gb[e];
        #pragma unroll 8
        for (int c = 0; c < NC; c++) s += pooled[c] * gw[e * NC + c];
        logits[e] = s;
    }
    __syncthreads();

    if (threadIdx.x == 0) {
        int i0 = 0; float v0 = logits[0];
        for (int e = 1; e < NE; e++) { if (logits[e] > v0) { v0 = logits[e]; i0 = e; } }
        int i1 = -1; float v1 = -INFINITY;
        for (int e = 0; e < NE; e++) {
            if (e == i0) continue;
            if (logits[e] > v1) { v1 = logits[e]; i1 = e; }
        }
        float w0 = 1.0f / (1.0f + expf(v1 - v0));
        float w1 = 1.0f - w0;
        g_eidx[b * 2 + 0] = i0;  g_eidx[b * 2 + 1] = i1;
        g_ewt [b * 2 + 0] = w0;  g_ewt [b * 2 + 1] = w1;
        if (dw_out) {
            dw_out[b * NE + i0] = w0;
            dw_out[b * NE + i1] = w1;
        }
    }
}

// ---------------------------------------------------------------------------
// Direct 3x3 conv, one block = (b, slot, output row y): 56 px x 64 cout.
// SMEM: full input strip (64 cin x 3 rows x 58 cols) + 16-cin weight chunks.
// Thread tile: 4 cout x 7 px (28 accumulators).
// MODE 1: y1 = relu(bn1(conv(x)))            -> g_y1
// MODE 2: z  = bn2(conv(y1)); out += wt*relu(z + x)   (atomicAdd, base 0)
// ---------------------------------------------------------------------------
#define SIN_ROW 58                 // 56 + 2 halo cols
#define SIN_SZ  (NC * 3 * SIN_ROW) // 11136 floats
#define WROW    145                // 16*9 + 1 pad
#define SW_SZ   (NC * WROW)        // 9280 floats
#define CONV_SMEM ((SIN_SZ + SW_SZ) * 4)

template <int MODE>
__global__ void __launch_bounds__(128, 2) conv_kernel(
    const float* __restrict__ x,      // original input [B,C,H,W]
    const float* __restrict__ w_all,  // [E,C,C,3,3]
    const float* __restrict__ bn_s,   // [E,C]
    const float* __restrict__ bn_b,   // [E,C]
    float* __restrict__ out)
{
    extern __shared__ float smem[];
    float* s_in = smem;           // [ci][r][col]  col in 0..57 (x = col-1)
    float* s_w  = smem + SIN_SZ;  // [co][ci_local*9 + k], pitch WROW

    const int y    = blockIdx.x;   // 0..55
    const int slot = blockIdx.y;   // 0..1
    const int b    = blockIdx.z;   // 0..63

    const int   e  = g_eidx[b * 2 + slot];
    const float wt = g_ewt [b * 2 + slot];

    const float* in = (MODE == 1) ? (x + (size_t)b * CHW)
                                  : (g_y1 + (size_t)(b * 2 + slot) * CHW);

    // stage input strip (rows y-1..y+1, zero-padded)
    for (int t = threadIdx.x; t < SIN_SZ; t += 128) {
        int ci  = t / (3 * SIN_ROW);
        int r2  = t - ci * (3 * SIN_ROW);
        int r   = r2 / SIN_ROW;
        int col = r2 - r * SIN_ROW;
        int yy = y + r - 1;
        int xx = col - 1;
        float v = 0.f;
        if (yy >= 0 && yy < NH && xx >= 0 && xx < NW)
            v = in[ci * HW + yy * NW + xx];
        s_in[t] = v;
    }

    const int tx  = threadIdx.x & 15;   // cout group
    const int ty  = threadIdx.x >> 4;   // px group
    const int co0 = tx * 4;
    const int x0  = ty * 7;

    float acc[4][7];
    #pragma unroll
    for (int c = 0; c < 4; c++)
        #pragma unroll
        for (int p = 0; p < 7; p++) acc[c][p] = 0.f;

    const float* wbase = w_all + (size_t)e * NC * NC * 9;

    for (int cc = 0; cc < 4; cc++) {          // 16-cin chunks
        __syncthreads();
        // stage weights: s_w[co*WROW + ci*9 + k] = w[e][co][cc*16+ci][k]
        for (int t = threadIdx.x; t < NC * 144; t += 128) {
            int co = t / 144;
            int r  = t - co * 144;            // ci*9 + k
            s_w[co * WROW + r] = wbase[co * 576 + cc * 144 + r];
        }
        __syncthreads();

        #pragma unroll 1
        for (int ci = 0; ci < 16; ci++) {
            const float* srow = s_in + (cc * 16 + ci) * (3 * SIN_ROW);
            const float* wrow0 = s_w + (co0 + 0) * WROW + ci * 9;
            const float* wrow1 = s_w + (co0 + 1) * WROW + ci * 9;
            const float* wrow2 = s_w + (co0 + 2) * WROW + ci * 9;
            const float* wrow3 = s_w + (co0 + 3) * WROW + ci * 9;
            #pragma unroll
            for (int ky = 0; ky < 3; ky++) {
                float xin[9];
                #pragma unroll
                for (int j = 0; j < 9; j++) xin[j] = srow[ky * SIN_ROW + x0 + j];
                #pragma unroll
                for (int kx = 0; kx < 3; kx++) {
                    int k = ky * 3 + kx;
                    float w0 = wrow0[k], w1 = wrow1[k], w2 = wrow2[k], w3 = wrow3[k];
                    #pragma unroll
                    for (int p = 0; p < 7; p++) {
                        float v = xin[p + kx];
                        acc[0][p] += w0 * v;
                        acc[1][p] += w1 * v;
                        acc[2][p] += w2 * v;
                        acc[3][p] += w3 * v;
                    }
                }
            }
        }
    }

    // epilogue
    if (MODE == 1) {
        float* dst = g_y1 + (size_t)(b * 2 + slot) * CHW;
        #pragma unroll
        for (int c = 0; c < 4; c++) {
            int co = co0 + c;
            float sc = bn_s[e * NC + co];
            float bi = bn_b[e * NC + co];
            #pragma unroll
            for (int p = 0; p < 7; p++) {
                float v = acc[c][p] * sc + bi;
                v = fmaxf(v, 0.f);
                dst[co * HW + y * NW + x0 + p] = v;
            }
        }
    } else {
        const float* xr = x + (size_t)b * CHW;
        float* dst = out + (size_t)b * CHW;
        #pragma unroll
        for (int c = 0; c < 4; c++) {
            int co = co0 + c;
            float sc = bn_s[e * NC + co];
            float bi = bn_b[e * NC + co];
            #pragma unroll
            for (int p = 0; p < 7; p++) {
                int idx = co * HW + y * NW + x0 + p;
                float z = acc[c][p] * sc + bi;
                float v = fmaxf(z + xr[idx], 0.f);
                atomicAdd(&dst[idx], wt * v);
            }
        }
    }
}

// ---------------------------------------------------------------------------
extern "C" void kernel_launch(void* const* d_in, const int* in_sizes, int n_in,
                              void* d_out, int out_size)
{
    const float* x       = (const float*)d_in[0];
    const float* gate_w  = (const float*)d_in[1];
    const float* gate_b  = (const float*)d_in[2];
    const float* conv1_w = (const float*)d_in[3];
    const float* bn1_s   = (const float*)d_in[4];
    const float* bn1_b   = (const float*)d_in[5];
    const float* conv2_w = (const float*)d_in[6];
    const float* bn2_s   = (const float*)d_in[7];
    const float* bn2_b   = (const float*)d_in[8];
    float* out = (float*)d_out;

    // zero output (atomic-combine base + dense_w scatter base)
    cudaMemsetAsync(d_out, 0, (size_t)out_size * sizeof(float), 0);

    float* dw_out = (out_size >= OUT_MAIN + NB * NE) ? (out + OUT_MAIN) : nullptr;
    gate_kernel<<<NB, 256>>>(x, gate_w, gate_b, dw_out);

    cudaFuncSetAttribute(conv_kernel<1>, cudaFuncAttributeMaxDynamicSharedMemorySize, CONV_SMEM);
    cudaFuncSetAttribute(conv_kernel<2>, cudaFuncAttributeMaxDynamicSharedMemorySize, CONV_SMEM);

    dim3 grid(NH, 2, NB);
    conv_kernel<1><<<grid, 128, CONV_SMEM>>>(x, conv1_w, bn1_s, bn1_b, nullptr);
    conv_kernel<2><<<grid, 128, CONV_SMEM>>>(x, conv2_w, bn2_s, bn2_b, out);
}

// round 2
// speedup vs baseline: 1.0113x; 1.0113x over previous
#include <cuda_runtime.h>
#include <cuda_bf16.h>
#include <math.h>

// Problem constants
#define NB   64
#define NC   64
#define NH   56
#define NW   56
#define NE   8
#define HW   (NH*NW)          // 3136
#define CHW  (NC*HW)          // 200704
#define OUT_MAIN (NB*CHW)     // 12845056

// Scratch: conv1 output per (b, slot)  -> 64*2*200704 floats = 411 MB
__device__ float g_y1[NB * 2 * CHW];
__device__ int   g_eidx[NB * 2];
__device__ float g_ewt[NB * 2];

// ---------------------------------------------------------------------------
// Gate: mean pool -> linear -> top-2 softmax. Writes expert routing globals
// and the nonzero dense_w entries (output tail is pre-zeroed by memset).
// ---------------------------------------------------------------------------
__global__ void gate_kernel(const float* __restrict__ x,
                            const float* __restrict__ gw,
                            const float* __restrict__ gb,
                            float* __restrict__ dw_out /* may be null */)
{
    int b = blockIdx.x;
    __shared__ float pooled[NC];
    __shared__ float logits[NE];

    int warp = threadIdx.x >> 5;
    int lane = threadIdx.x & 31;

    // warp per channel (8 warps x 8 channels each)
    for (int c = warp; c < NC; c += 8) {
        const float* p = x + ((size_t)b * NC + c) * HW;
        float s = 0.f;
        for (int i = lane; i < HW; i += 32) s += p[i];
        #pragma unroll
        for (int o = 16; o > 0; o >>= 1) s += __shfl_xor_sync(0xffffffffu, s, o);
        if (lane == 0) pooled[c] = s * (1.0f / (float)HW);
    }
    __syncthreads();

    if (threadIdx.x < NE) {
        int e = threadIdx.x;
        float s = gb[e];
        #pragma unroll 8
        for (int c = 0; c < NC; c++) s += pooled[c] * gw[e * NC + c];
        logits[e] = s;
    }
    __syncthreads();

    if (threadIdx.x == 0) {
        int i0 = 0; float v0 = logits[0];
        for (int e = 1; e < NE; e++) { if (logits[e] > v0) { v0 = logits[e]; i0 = e; } }
        int i1 = -1; float v1 = -INFINITY;
        for (int e = 0; e < NE; e++) {
            if (e == i0) continue;
            if (logits[e] > v1) { v1 = logits[e]; i1 = e; }
        }
        float w0 = 1.0f / (1.0f + expf(v1 - v0));
        float w1 = 1.0f - w0;
        g_eidx[b * 2 + 0] = i0;  g_eidx[b * 2 + 1] = i1;
        g_ewt [b * 2 + 0] = w0;  g_ewt [b * 2 + 1] = w1;
        if (dw_out) {
            dw_out[b * NE + i0] = w0;
            dw_out[b * NE + i1] = w1;
        }
    }
}

// ---------------------------------------------------------------------------
// Direct 3x3 conv, one block = (b, slot, output row y): 56 px x 64 cout.
// SMEM: full input strip (64 cin x 3 rows x 58 cols) + 16-cin weight chunks.
// Thread tile: 4 cout x 7 px (28 accumulators).
// MODE 1: y1 = relu(bn1(conv(x)))            -> g_y1
// MODE 2: z  = bn2(conv(y1)); out += wt*relu(z + x)   (atomicAdd, base 0)
// ---------------------------------------------------------------------------
#define SIN_ROW 58                 // 56 + 2 halo cols
#define SIN_SZ  (NC * 3 * SIN_ROW) // 11136 floats
#define WROW    145                // 16*9 + 1 pad
#define SW_SZ   (NC * WROW)        // 9280 floats
#define CONV_SMEM ((SIN_SZ + SW_SZ) * 4)

template <int MODE>
__global__ void __launch_bounds__(128, 2) conv_kernel(
    const float* __restrict__ x,      // original input [B,C,H,W]
    const float* __restrict__ w_all,  // [E,C,C,3,3]
    const float* __restrict__ bn_s,   // [E,C]
    const float* __restrict__ bn_b,   // [E,C]
    float* __restrict__ out)
{
    extern __shared__ float smem[];
    float* s_in = smem;           // [ci][r][col]  col in 0..57 (x = col-1)
    float* s_w  = smem + SIN_SZ;  // [co][ci_local*9 + k], pitch WROW

    const int y    = blockIdx.x;   // 0..55
    const int slot = blockIdx.y;   // 0..1
    const int b    = blockIdx.z;   // 0..63

    const int   e  = g_eidx[b * 2 + slot];
    const float wt = g_ewt [b * 2 + slot];

    const float* in = (MODE == 1) ? (x + (size_t)b * CHW)
                                  : (g_y1 + (size_t)(b * 2 + slot) * CHW);

    // stage input strip (rows y-1..y+1, zero-padded)
    for (int t = threadIdx.x; t < SIN_SZ; t += 128) {
        int ci  = t / (3 * SIN_ROW);
        int r2  = t - ci * (3 * SIN_ROW);
        int r   = r2 / SIN_ROW;
        int col = r2 - r * SIN_ROW;
        int yy = y + r - 1;
        int xx = col - 1;
        float v = 0.f;
        if (yy >= 0 && yy < NH && xx >= 0 && xx < NW)
            v = in[ci * HW + yy * NW + xx];
        s_in[t] = v;
    }

    const int tx  = threadIdx.x & 15;   // cout group
    const int ty  = threadIdx.x >> 4;   // px group
    const int co0 = tx * 4;
    const int x0  = ty * 7;

    float acc[4][7];
    #pragma unroll
    for (int c = 0; c < 4; c++)
        #pragma unroll
        for (int p = 0; p < 7; p++) acc[c][p] = 0.f;

    const float* wbase = w_all + (size_t)e * NC * NC * 9;

    for (int cc = 0; cc < 4; cc++) {          // 16-cin chunks
        __syncthreads();
        // stage weights: s_w[co*WROW + ci*9 + k] = w[e][co][cc*16+ci][k]
        for (int t = threadIdx.x; t < NC * 144; t += 128) {
            int co = t / 144;
            int r  = t - co * 144;            // ci*9 + k
            s_w[co * WROW + r] = wbase[co * 576 + cc * 144 + r];
        }
        __syncthreads();

        #pragma unroll 1
        for (int ci = 0; ci < 16; ci++) {
            const float* srow = s_in + (cc * 16 + ci) * (3 * SIN_ROW);
            const float* wrow0 = s_w + (co0 + 0) * WROW + ci * 9;
            const float* wrow1 = s_w + (co0 + 1) * WROW + ci * 9;
            const float* wrow2 = s_w + (co0 + 2) * WROW + ci * 9;
            const float* wrow3 = s_w + (co0 + 3) * WROW + ci * 9;
            #pragma unroll
            for (int ky = 0; ky < 3; ky++) {
                float xin[9];
                #pragma unroll
                for (int j = 0; j < 9; j++) xin[j] = srow[ky * SIN_ROW + x0 + j];
                #pragma unroll
                for (int kx = 0; kx < 3; kx++) {
                    int k = ky * 3 + kx;
                    float w0 = wrow0[k], w1 = wrow1[k], w2 = wrow2[k], w3 = wrow3[k];
                    #pragma unroll
                    for (int p = 0; p < 7; p++) {
                        float v = xin[p + kx];
                        acc[0][p] += w0 * v;
                        acc[1][p] += w1 * v;
                        acc[2][p] += w2 * v;
                        acc[3][p] += w3 * v;
                    }
                }
            }
        }
    }

    // epilogue
    if (MODE == 1) {
        float* dst = g_y1 + (size_t)(b * 2 + slot) * CHW;
        #pragma unroll
        for (int c = 0; c < 4; c++) {
            int co = co0 + c;
            float sc = bn_s[e * NC + co];
            float bi = bn_b[e * NC + co];
            #pragma unroll
            for (int p = 0; p < 7; p++) {
                float v = acc[c][p] * sc + bi;
                v = fmaxf(v, 0.f);
                dst[co * HW + y * NW + x0 + p] = v;
            }
        }
    } else {
        const float* xr = x + (size_t)b * CHW;
        float* dst = out + (size_t)b * CHW;
        #pragma unroll
        for (int c = 0; c < 4; c++) {
            int co = co0 + c;
            float sc = bn_s[e * NC + co];
            float bi = bn_b[e * NC + co];
            #pragma unroll
            for (int p = 0; p < 7; p++) {
                int idx = co * HW + y * NW + x0 + p;
                float z = acc[c][p] * sc + bi;
                float v = fmaxf(z + xr[idx], 0.f);
                atomicAdd(&dst[idx], wt * v);
            }
        }
    }
}

// ---------------------------------------------------------------------------
extern "C" void kernel_launch(void* const* d_in, const int* in_sizes, int n_in,
                              void* d_out, int out_size)
{
    const float* x       = (const float*)d_in[0];
    const float* gate_w  = (const float*)d_in[1];
    const float* gate_b  = (const float*)d_in[2];
    const float* conv1_w = (const float*)d_in[3];
    const float* bn1_s   = (const float*)d_in[4];
    const float* bn1_b   = (const float*)d_in[5];
    const float* conv2_w = (const float*)d_in[6];
    const float* bn2_s   = (const float*)d_in[7];
    const float* bn2_b   = (const float*)d_in[8];
    float* out = (float*)d_out;

    // zero output (atomic-combine base + dense_w scatter base)
    cudaMemsetAsync(d_out, 0, (size_t)out_size * sizeof(float), 0);

    float* dw_out = (out_size >= OUT_MAIN + NB * NE) ? (out + OUT_MAIN) : nullptr;
    gate_kernel<<<NB, 256>>>(x, gate_w, gate_b, dw_out);

    cudaFuncSetAttribute(conv_kernel<1>, cudaFuncAttributeMaxDynamicSharedMemorySize, CONV_SMEM);
    cudaFuncSetAttribute(conv_kernel<2>, cudaFuncAttributeMaxDynamicSharedMemorySize, CONV_SMEM);

    dim3 grid(NH, 2, NB);
    conv_kernel<1><<<grid, 128, CONV_SMEM>>>(x, conv1_w, bn1_s, bn1_b, nullptr);
    conv_kernel<2><<<grid, 128, CONV_SMEM>>>(x, conv2_w, bn2_s, bn2_b, out);
}

// round 4
// speedup vs baseline: 3.3467x; 3.3094x over previous
#include <cuda_runtime.h>
#include <cuda_bf16.h>
#include <math.h>
#include <stdint.h>

#define NB 64
#define NC 64
#define NH 56
#define NW 56
#define HW 3136
#define CHW 200704
#define OUT_MAIN (NB*CHW)

__device__ float g_y1[NB*2*CHW];
__device__ int   g_eidx[NB*2];
__device__ float g_ewt[NB*2];
__device__ float g_pooled[NB*NC];

// ---- SMEM layout (bytes) ----
#define SM_W    0
#define WTILE   16384                 // per tap: Wh 8KB (64x128B) + Wl 8KB
#define SM_RING (9*WTILE)             // 147456
#define SLOT_H  9216                  // 72 rows x 128B
#define SLOT    18432                 // hi + lo
#define SM_TOTAL (SM_RING + 4*SLOT)   // 221184

__device__ __forceinline__ uint32_t smem_u32(const void* p){
    uint32_t a; asm("{ .reg .u64 t; cvta.to.shared.u64 t, %1; cvt.u32.u64 %0, t; }":"=r"(a):"l"(p)); return a;
}

#define LDSM4(d0,d1,d2,d3,a) \
    asm volatile("ldmatrix.sync.aligned.m8n8.x4.shared.b16 {%0,%1,%2,%3},[%4];" \
        : "=r"(d0),"=r"(d1),"=r"(d2),"=r"(d3) : "r"(a))

#define MMA16816(C,a0,a1,a2,a3,b0,b1) \
    asm volatile("mma.sync.aligned.m16n8k16.row.col.f32.bf16.bf16.f32 " \
        "{%0,%1,%2,%3},{%4,%5,%6,%7},{%8,%9},{%0,%1,%2,%3};" \
        : "+f"((C)[0]),"+f"((C)[1]),"+f"((C)[2]),"+f"((C)[3]) \
        : "r"(a0),"r"(a1),"r"(a2),"r"(a3),"r"(b0),"r"(b1))

// ---------------------------------------------------------------------------
// Gate: pooling (grid 64x8) + finalize (1x64)
// ---------------------------------------------------------------------------
__global__ void pool_kernel(const float* __restrict__ x){
    int b = blockIdx.x, gg = blockIdx.y;
    int w = threadIdx.x>>5, l = threadIdx.x&31;
    int c = gg*8 + w;
    const float4* p = (const float4*)(x + ((size_t)b*NC + c)*HW);
    float s = 0.f;
    for (int i=l; i<HW/4; i+=32){ float4 v = p[i]; s += (v.x+v.y)+(v.z+v.w); }
    #pragma unroll
    for (int o=16;o>0;o>>=1) s += __shfl_xor_sync(0xffffffffu, s, o);
    if (l==0) g_pooled[b*NC+c] = s * (1.0f/(float)HW);
}

__global__ void gate_fin(const float* __restrict__ gw, const float* __restrict__ gb,
                         float* __restrict__ dw){
    int b = threadIdx.x;
    if (b >= NB) return;
    float lg[8];
    #pragma unroll
    for (int e=0;e<8;e++){
        float s = gb[e];
        for (int c=0;c<NC;c++) s += g_pooled[b*NC+c]*gw[e*NC+c];
        lg[e] = s;
    }
    int i0=0; float v0=lg[0];
    #pragma unroll
    for (int e=1;e<8;e++) if (lg[e]>v0){ v0=lg[e]; i0=e; }
    int i1=-1; float v1=-1e30f;
    #pragma unroll
    for (int e=0;e<8;e++){ if (e==i0) continue; if (lg[e]>v1){ v1=lg[e]; i1=e; } }
    float w0 = 1.0f/(1.0f+expf(v1-v0));
    float w1 = 1.0f-w0;
    g_eidx[b*2+0]=i0; g_eidx[b*2+1]=i1;
    g_ewt [b*2+0]=w0; g_ewt [b*2+1]=w1;
    if (dw){ dw[b*8+i0]=w0; dw[b*8+i1]=w1; }
}

// ---------------------------------------------------------------------------
// Stage input row yy into ring slot (yy&3): rows c = x+1 (1..56), cols = cin.
// Rows 0, 57..71 stay zero (initialized once). bf16 hi + lo split.
// ---------------------------------------------------------------------------
__device__ __forceinline__ void stage_row(char* smem, const float* __restrict__ in, int yy){
    int ci = threadIdx.x >> 1, half = threadIdx.x & 1;
    uint32_t base = SM_RING + (uint32_t)(yy&3)*SLOT;
    const float* src = in + (size_t)ci*HW + yy*NW + half*28;
    uint32_t cb2 = (uint32_t)(ci*2);
    #pragma unroll 7
    for (int j=0;j<28;j++){
        int x = half*28 + j;
        float v = src[j];
        __nv_bfloat16 h = __float2bfloat16(v);
        __nv_bfloat16 l = __float2bfloat16(v - __bfloat162float(h));
        uint32_t c = (uint32_t)(x+1);
        uint32_t off = base + c*128 + (cb2 ^ ((c&7)<<4));
        *(__nv_bfloat16*)(smem+off) = h;
        *(__nv_bfloat16*)(smem+off+SLOT_H) = l;
    }
}

// ---------------------------------------------------------------------------
// Persistent conv per (b,slot), HMMA. 4 warps, warp tile M32xN32.
// MODE1: g_y1 = relu(bn1(conv(x)))
// MODE2: out += wt * relu(bn2(conv(g_y1)) + x)
// ---------------------------------------------------------------------------
template<int MODE>
__global__ void __launch_bounds__(128,1) conv_hmma(
    const float* __restrict__ x, const float* __restrict__ w_all,
    const float* __restrict__ bn_s, const float* __restrict__ bn_b,
    float* __restrict__ out)
{
    extern __shared__ char smem[];
    const int tid = threadIdx.x, wid = tid>>5, lane = tid&31;
    const int wm = wid>>1, wn = wid&1;         // M tile wm*32, N tile wn*32
    const int bs = blockIdx.x, b = bs>>1;
    const int e = g_eidx[bs];
    const float wt = g_ewt[bs];
    const float* in   = (MODE==1) ? x + (size_t)b*CHW : g_y1 + (size_t)bs*CHW;
    const float* xres = x + (size_t)b*CHW;
    float* dst = (MODE==1) ? g_y1 + (size_t)bs*CHW : out + (size_t)b*CHW;
    const uint32_t sbase = smem_u32(smem);

    // zero ring (rows never re-written stay zero: halo + n>=56 pad)
    for (int i=tid; i<(4*SLOT)/4; i+=128) ((uint32_t*)(smem+SM_RING))[i] = 0;

    // stage weights once: tap g tile = [Wh rows co | +8192 Wl], swizzled
    const float* wb = w_all + (size_t)e*NC*NC*9;
    for (int p=tid; p<4096; p+=128){
        int co = p>>6, ci = p&63;
        const float* wp = wb + (size_t)p*9;
        uint32_t sx = (uint32_t)((co&7)<<4);
        uint32_t ro = (uint32_t)co*128;
        uint32_t cb = (uint32_t)(ci*2);
        #pragma unroll
        for (int g9=0; g9<9; g9++){
            float v = wp[g9];
            __nv_bfloat16 h = __float2bfloat16(v);
            __nv_bfloat16 l = __float2bfloat16(v - __bfloat162float(h));
            uint32_t off = SM_W + (uint32_t)g9*WTILE + ro + (cb ^ sx);
            *(__nv_bfloat16*)(smem+off) = h;
            *(__nv_bfloat16*)(smem+off+8192) = l;
        }
    }
    stage_row(smem, in, 0);
    stage_row(smem, in, 1);

    // per-thread bn params (co fixed for whole kernel)
    const int g = lane>>2;
    float scv[2][2], biv[2][2];
    #pragma unroll
    for (int mt=0; mt<2; mt++){
        int co0 = wm*32 + mt*16 + g;
        scv[mt][0] = bn_s[e*NC+co0];   biv[mt][0] = bn_b[e*NC+co0];
        scv[mt][1] = bn_s[e*NC+co0+8]; biv[mt][1] = bn_b[e*NC+co0+8];
    }
    __syncthreads();

    // per-lane ldmatrix constants
    const int sub = lane>>3, r = lane&7;
    uint32_t rAoff[2], sxA[2];
    #pragma unroll
    for (int mt=0; mt<2; mt++){
        uint32_t rowA = (uint32_t)(wm*32 + mt*16 + (sub&1)*8 + r);
        rAoff[mt] = rowA*128;
        sxA[mt]   = (rowA&7)<<4;
    }
    const uint32_t kbA0 = (uint32_t)((sub>>1)*16);
    const uint32_t rb0  = (uint32_t)(wn*32 + (sub>>1)*8 + r);
    const uint32_t kbB0 = (uint32_t)((sub&1)*16);

    for (int y=0; y<NH; y++){
        if (y+2 < NH) stage_row(smem, in, y+2);

        float C[2][4][4];
        #pragma unroll
        for (int mt=0;mt<2;mt++)
            #pragma unroll
            for (int j=0;j<4;j++)
                #pragma unroll
                for (int q=0;q<4;q++) C[mt][j][q]=0.f;

        for (int ky=0; ky<3; ky++){
            int yy = y+ky-1;
            if (yy<0 || yy>=NH) continue;
            uint32_t slotB = sbase + SM_RING + (uint32_t)(yy&3)*SLOT;
            #pragma unroll
            for (int kx=0; kx<3; kx++){
                uint32_t aT = sbase + SM_W + (uint32_t)(3*ky+kx)*WTILE;
                #pragma unroll
                for (int ks=0; ks<4; ks++){
                    uint32_t kA = kbA0 + (uint32_t)ks*32;
                    uint32_t kB = kbB0 + (uint32_t)ks*32;
                    uint32_t ah[2][4], al[2][4], bh[2][4], bl[2][4];
                    #pragma unroll
                    for (int mt=0; mt<2; mt++){
                        uint32_t a0 = aT + rAoff[mt] + (kA ^ sxA[mt]);
                        LDSM4(ah[mt][0],ah[mt][1],ah[mt][2],ah[mt][3], a0);
                        LDSM4(al[mt][0],al[mt][1],al[mt][2],al[mt][3], a0 + 8192);
                    }
                    #pragma unroll
                    for (int nt=0; nt<2; nt++){
                        uint32_t rb = rb0 + (uint32_t)(kx + nt*16);
                        uint32_t b0 = slotB + rb*128 + (kB ^ ((rb&7)<<4));
                        LDSM4(bh[nt][0],bh[nt][1],bh[nt][2],bh[nt][3], b0);
                        LDSM4(bl[nt][0],bl[nt][1],bl[nt][2],bl[nt][3], b0 + SLOT_H);
                    }
                    #pragma unroll
                    for (int mt=0;mt<2;mt++){
                        #pragma unroll
                        for (int nt=0;nt<2;nt++){
                            float* Cl = C[mt][nt*2];
                            float* Ch = C[mt][nt*2+1];
                            // n8-lo tile: b regs {0,1}; n8-hi: {2,3}
                            MMA16816(Cl, ah[mt][0],ah[mt][1],ah[mt][2],ah[mt][3], bh[nt][0],bh[nt][1]);
                            MMA16816(Cl, ah[mt][0],ah[mt][1],ah[mt][2],ah[mt][3], bl[nt][0],bl[nt][1]);
                            MMA16816(Cl, al[mt][0],al[mt][1],al[mt][2],al[mt][3], bh[nt][0],bh[nt][1]);
                            MMA16816(Ch, ah[mt][0],ah[mt][1],ah[mt][2],ah[mt][3], bh[nt][2],bh[nt][3]);
                            MMA16816(Ch, ah[mt][0],ah[mt][1],ah[mt][2],ah[mt][3], bl[nt][2],bl[nt][3]);
                            MMA16816(Ch, al[mt][0],al[mt][1],al[mt][2],al[mt][3], bh[nt][2],bh[nt][3]);
                        }
                    }
                }
            }
        }

        // epilogue: bn + (store | residual+relu+wt atomic add)
        int xq = 2*(lane&3);
        #pragma unroll
        for (int mt=0;mt<2;mt++){
            int co0 = wm*32 + mt*16 + g, co1 = co0+8;
            #pragma unroll
            for (int j=0;j<4;j++){
                int xx = wn*32 + j*8 + xq;
                if (xx >= NW) continue;
                float v0 = C[mt][j][0]*scv[mt][0] + biv[mt][0];
                float v1 = C[mt][j][1]*scv[mt][0] + biv[mt][0];
                float v2 = C[mt][j][2]*scv[mt][1] + biv[mt][1];
                float v3 = C[mt][j][3]*scv[mt][1] + biv[mt][1];
                int i0 = co0*HW + y*NW + xx;
                int i1 = co1*HW + y*NW + xx;
                if (MODE==1){
                    *(float2*)(dst+i0) = make_float2(fmaxf(v0,0.f), fmaxf(v1,0.f));
                    *(float2*)(dst+i1) = make_float2(fmaxf(v2,0.f), fmaxf(v3,0.f));
                } else {
                    float2 r0 = *(const float2*)(xres+i0);
                    float2 r1 = *(const float2*)(xres+i1);
                    atomicAdd(dst+i0,   wt*fmaxf(v0+r0.x,0.f));
                    atomicAdd(dst+i0+1, wt*fmaxf(v1+r0.y,0.f));
                    atomicAdd(dst+i1,   wt*fmaxf(v2+r1.x,0.f));
                    atomicAdd(dst+i1+1, wt*fmaxf(v3+r1.y,0.f));
                }
            }
        }
        __syncthreads();
    }
}

// ---------------------------------------------------------------------------
extern "C" void kernel_launch(void* const* d_in, const int* in_sizes, int n_in,
                              void* d_out, int out_size)
{
    const float* x       = (const float*)d_in[0];
    const float* gate_w  = (const float*)d_in[1];
    const float* gate_b  = (const float*)d_in[2];
    const float* conv1_w = (const float*)d_in[3];
    const float* bn1_s   = (const float*)d_in[4];
    const float* bn1_b   = (const float*)d_in[5];
    const float* conv2_w = (const float*)d_in[6];
    const float* bn2_s   = (const float*)d_in[7];
    const float* bn2_b   = (const float*)d_in[8];
    float* out = (float*)d_out;

    cudaMemsetAsync(d_out, 0, (size_t)out_size*sizeof(float), 0);
    pool_kernel<<<dim3(NB,8), 256>>>(x);
    float* dw = (out_size >= OUT_MAIN + NB*8) ? (out + OUT_MAIN) : nullptr;
    gate_fin<<<1, 64>>>(gate_w, gate_b, dw);

    cudaFuncSetAttribute(conv_hmma<1>, cudaFuncAttributeMaxDynamicSharedMemorySize, SM_TOTAL);
    cudaFuncSetAttribute(conv_hmma<2>, cudaFuncAttributeMaxDynamicSharedMemorySize, SM_TOTAL);
    conv_hmma<1><<<128, 128, SM_TOTAL>>>(x, conv1_w, bn1_s, bn1_b, nullptr);
    conv_hmma<2><<<128, 128, SM_TOTAL>>>(x, conv2_w, bn2_s, bn2_b, out);
}